// round 1
// baseline (speedup 1.0000x reference)
#include <cuda_runtime.h>

// C51 categorical projection.
// Row-local scatter -> streaming two-accumulator merge (no atomics), exploiting
// monotone bin index l(a) with step in {0,1} and u == l+1 after disambiguation.
// Shared-memory staging gives fully coalesced float4 global traffic.

static constexpr int ATOMS_C = 51;
static constexpr int ROWS    = 64;                 // rows (= threads) per block
static constexpr int TILE    = ROWS * ATOMS_C;     // 3264 floats, 13056 B (16B-aligned)

__global__ __launch_bounds__(ROWS) void c51_project_kernel(
    const float* __restrict__ g_reward,
    const float* __restrict__ g_dist,
    const float* __restrict__ g_sup,
    const int*   __restrict__ g_mask,
    float*       __restrict__ g_out)
{
    __shared__ float s_dist[TILE];
    __shared__ float s_out[TILE];
    __shared__ float s_rew[ROWS];
    __shared__ float s_msk[ROWS];
    __shared__ float s_sup99[ATOMS_C];

    const int tid = threadIdx.x;
    const long long base = (long long)blockIdx.x * TILE;

    // ---- Coalesced float4 load of the dist tile; zero the output tile ----
    const float4* g4  = reinterpret_cast<const float4*>(g_dist + base);
    float4*       sd4 = reinterpret_cast<float4*>(s_dist);
    float4*       so4 = reinterpret_cast<float4*>(s_out);
    const float4  z4  = make_float4(0.f, 0.f, 0.f, 0.f);
    for (int i = tid; i < TILE / 4; i += ROWS) {
        sd4[i] = g4[i];
        so4[i] = z4;
    }
    {
        const int r = blockIdx.x * ROWS + tid;
        s_rew[tid] = g_reward[r];
        s_msk[tid] = (float)g_mask[r];
    }
    if (tid < ATOMS_C) s_sup99[tid] = 0.99f * g_sup[tid];   // gamma^nsteps * z
    __syncthreads();

    // ---- Per-thread row: streaming projection ----
    const float rw = s_rew[tid];
    const float mk = s_msk[tid];
    const float* __restrict__ drow = s_dist + tid * ATOMS_C; // stride 51 -> bank-conflict-free
    float*       __restrict__ orow = s_out  + tid * ATOMS_C;

    float acc0 = 0.f;   // pending weight for bin 'cur'
    float acc1 = 0.f;   // pending weight for bin 'cur+1'
    int   cur  = 0;

    #pragma unroll 3
    for (int a = 0; a < ATOMS_C; ++a) {
        float Tz = fmaf(s_sup99[a], mk, rw);          // s*m exact (m in {0,1})
        Tz = fminf(fmaxf(Tz, -10.0f), 10.0f);
        const float b  = (Tz + 10.0f) / 0.4f;         // (Tz - V_MIN) / DELTA
        float lf = floorf(b);
        float uf = ceilf(b);
        int   l  = (int)lf;
        const int u = (int)uf;
        if (l == u) {                                  // exact-integer bin
            if (u > 0) { --l; lf -= 1.0f; }            // reference: l-adjust first
            else       { uf += 1.0f; }                 // then u-adjust (l==u==0 case)
        }
        const float d  = drow[a];
        const float wl = d * (uf - b);
        const float wu = d * (b - lf);

        // l is monotone non-decreasing; flush completed bins (s_out pre-zeroed,
        // so large first jumps are handled too).
        while (cur < l) {
            orow[cur] = acc0;
            acc0 = acc1;
            acc1 = 0.f;
            ++cur;
        }
        acc0 += wl;
        acc1 += wu;
    }
    orow[cur]     = acc0;   // cur <= 49 guaranteed (b<=50 -> l<=49 after adjust)
    orow[cur + 1] = acc1;

    __syncthreads();

    // ---- Coalesced float4 store ----
    float4* go4 = reinterpret_cast<float4*>(g_out + base);
    for (int i = tid; i < TILE / 4; i += ROWS) go4[i] = so4[i];
}

extern "C" void kernel_launch(void* const* d_in, const int* in_sizes, int n_in,
                              void* d_out, int out_size) {
    const float* reward = (const float*)d_in[0];   // batch_reward  [B] f32
    const float* dist   = (const float*)d_in[1];   // max_next_dist [B,51] f32
    const float* sup    = (const float*)d_in[2];   // supports      [51] f32
    const int*   mask   = (const int*)d_in[3];     // non_final_mask[B] i32
    float* out = (float*)d_out;                    // [B,51] f32

    const int B = in_sizes[0];                     // 1048576 (divisible by 64)
    const int blocks = B / ROWS;
    c51_project_kernel<<<blocks, ROWS>>>(reward, dist, sup, mask, out);
}

// round 2
// speedup vs baseline: 2.1785x; 2.1785x over previous
#include <cuda_runtime.h>

// C51 categorical projection, round 2.
// Branch-free streaming merge: after atom 0, the lower bin index l advances by
// exactly 0 or 1 per atom (bin step = 0.99 < 1, clip is 1-Lipschitz), so the
// flush is a single predicated shared store + two selects — no divergence.
// Unified disambiguation: u == l' + 1 always, where
//   l' = floor(b) - (b is exact integer && b > 0).

static constexpr int ATOMS_C = 51;
static constexpr int ROWS    = 64;                 // rows (= threads) per block
static constexpr int TILE    = ROWS * ATOMS_C;     // 3264 floats (13056 B)

__global__ __launch_bounds__(ROWS) void c51_project_kernel(
    const float* __restrict__ g_reward,
    const float* __restrict__ g_dist,
    const float* __restrict__ g_sup,
    const int*   __restrict__ g_mask,
    float*       __restrict__ g_out)
{
    __shared__ float s_dist[TILE];
    __shared__ float s_out[TILE];
    __shared__ float s_sup99[ATOMS_C];

    const int tid = threadIdx.x;
    const long long base = (long long)blockIdx.x * TILE;

    // ---- Coalesced float4 load of the dist tile; zero the output tile ----
    const float4* g4  = reinterpret_cast<const float4*>(g_dist + base);
    float4*       sd4 = reinterpret_cast<float4*>(s_dist);
    float4*       so4 = reinterpret_cast<float4*>(s_out);
    const float4  z4  = make_float4(0.f, 0.f, 0.f, 0.f);
    #pragma unroll 4
    for (int i = tid; i < TILE / 4; i += ROWS) {
        sd4[i] = g4[i];
        so4[i] = z4;
    }
    if (tid < ATOMS_C) s_sup99[tid] = 0.99f * g_sup[tid];   // gamma^nsteps * z
    __syncthreads();

    // reward/mask: directly coalesced (256 B per block)
    const int   r  = blockIdx.x * ROWS + tid;
    const float rw = __ldg(g_reward + r);
    const float mk = (float)__ldg(g_mask + r);

    const float* __restrict__ drow = s_dist + tid * ATOMS_C;
    float*       __restrict__ orow = s_out  + tid * ATOMS_C;

    // projection of one atom -> (b, lf) with unified u = lf + 1
    auto proj = [&](int a, float& b, float& lf) {
        float Tz = fmaf(s_sup99[a], mk, rw);           // s*m exact (m in {0,1})
        Tz = fminf(fmaxf(Tz, -10.0f), 10.0f);
        b  = (Tz + 10.0f) / 0.4f;                      // (Tz - V_MIN) / DELTA
        lf = floorf(b);
        if (b == lf && b > 0.0f) lf -= 1.0f;           // exact-integer bin
    };

    // ---- atom 0: establishes the initial bin (earlier bins stay zero) ----
    float b, lf;
    proj(0, b, lf);
    float  curf = lf;
    float* wptr = orow + (int)lf;                      // single F2I total
    float  d0   = drow[0];
    float  acc0 = d0 * (lf + 1.0f - b);                // weight -> bin cur
    float  acc1 = d0 * (b - lf);                       // weight -> bin cur+1

    // ---- atoms 1..50: l advances by 0 or 1; fully predicated flush ----
    #pragma unroll
    for (int a = 1; a < ATOMS_C; ++a) {
        proj(a, b, lf);
        const float d  = drow[a];
        const float wl = d * (lf + 1.0f - b);
        const float wu = d * (b - lf);
        const bool adv = (lf != curf);                 // advance by exactly 1
        if (adv) *wptr = acc0;                         // @P STS, no divergence
        acc0 = (adv ? acc1 : acc0) + wl;
        acc1 = adv ? wu : (acc1 + wu);
        wptr = adv ? (wptr + 1) : wptr;
        curf = lf;
    }
    wptr[0] = acc0;                                    // cur <= 49, cur+1 <= 50
    wptr[1] = acc1;

    __syncthreads();

    // ---- Coalesced float4 store ----
    float4* go4 = reinterpret_cast<float4*>(g_out + base);
    #pragma unroll 4
    for (int i = tid; i < TILE / 4; i += ROWS) go4[i] = so4[i];
}

extern "C" void kernel_launch(void* const* d_in, const int* in_sizes, int n_in,
                              void* d_out, int out_size) {
    const float* reward = (const float*)d_in[0];   // batch_reward  [B] f32
    const float* dist   = (const float*)d_in[1];   // max_next_dist [B,51] f32
    const float* sup    = (const float*)d_in[2];   // supports      [51] f32
    const int*   mask   = (const int*)d_in[3];     // non_final_mask[B] i32
    float* out = (float*)d_out;                    // [B,51] f32

    const int B = in_sizes[0];                     // 1048576 (divisible by 64)
    const int blocks = B / ROWS;
    c51_project_kernel<<<blocks, ROWS>>>(reward, dist, sup, mask, out);
}

// round 3
// speedup vs baseline: 3.2246x; 1.4802x over previous
#include <cuda_runtime.h>

// C51 categorical projection, round 3.
// b(a) = clamp(step*a + base, 0, 50-eps) — affine form removes the per-atom
// division and supports LDS (clip commutes with the affine map to bin space).
// Exact-integer disambiguation is value-irrelevant (all weight lands on bin k
// either way), so l = floor(b), u = l+1 unconditionally; the 49.999996 clamp
// keeps l <= 49 at the top endpoint.
// Streaming two-accumulator merge: l advances by 0 or 1 per atom -> fully
// predicated flush, no divergence, no atomics.

static constexpr int ATOMS_C = 51;
static constexpr int ROWS    = 64;                 // rows (= threads) per block
static constexpr int TILE    = ROWS * ATOMS_C;     // 3264 floats (13056 B)

__global__ __launch_bounds__(ROWS) void c51_project_kernel(
    const float* __restrict__ g_reward,
    const float* __restrict__ g_dist,
    const int*   __restrict__ g_mask,
    float*       __restrict__ g_out)
{
    __shared__ float s_dist[TILE];
    __shared__ float s_out[TILE];

    const int tid = threadIdx.x;
    const long long base_g = (long long)blockIdx.x * TILE;

    // ---- Coalesced float4 load of the dist tile; zero the output tile ----
    const float4* g4  = reinterpret_cast<const float4*>(g_dist + base_g);
    float4*       sd4 = reinterpret_cast<float4*>(s_dist);
    float4*       so4 = reinterpret_cast<float4*>(s_out);
    const float4  z4  = make_float4(0.f, 0.f, 0.f, 0.f);
    #pragma unroll 4
    for (int i = tid; i < TILE / 4; i += ROWS) {
        sd4[i] = g4[i];
        so4[i] = z4;
    }
    __syncthreads();

    // ---- Per-row affine bin map: b(a) = clamp(step*a + base, 0, HI) ----
    const int   r    = blockIdx.x * ROWS + tid;
    const float rw   = __ldg(g_reward + r);
    const float mk   = (float)__ldg(g_mask + r);
    const float step = 0.99f * mk;
    const float base = (rw + 10.0f) / 0.4f - 24.75f * mk;  // one div per row
    const float HI   = 49.999996f;                          // largest f32 < 50

    const float* __restrict__ drow = s_dist + tid * ATOMS_C; // stride 51: no conflicts
    float*       __restrict__ orow = s_out  + tid * ATOMS_C;

    // ---- atom 0: establish the initial bin ----
    float b    = fminf(fmaxf(base, 0.0f), HI);
    float curf = floorf(b);
    float* wptr = orow + (int)curf;            // single F2I per row
    {
        const float d    = drow[0];
        const float bmlf = b - curf;
        float acc1_0 = d * bmlf;
        float acc0_0 = d - acc1_0;
        // fallthrough into loop via registers:
        float acc0 = acc0_0, acc1 = acc1_0;

        // ---- atoms 1..50: l advances by 0 or 1 (step = 0.99 < 1) ----
        #pragma unroll
        for (int a = 1; a < ATOMS_C; ++a) {
            float bb = fmaf(step, (float)a, base);   // FFMA with imm multiplier
            bb = fminf(fmaxf(bb, 0.0f), HI);
            const float lfn = floorf(bb);            // independent per atom
            const float d2  = drow[a];
            const float bm  = bb - lfn;
            const float wu  = d2 * bm;
            const float wl  = d2 - wu;               // d*(lf+1-b)
            const bool adv  = (lfn != curf);
            if (adv) *wptr = acc0;                   // @P STS, converged
            const float a0 = adv ? acc1 : acc0;
            acc0 = a0 + wl;
            const float t  = acc1 + wu;
            acc1 = adv ? wu : t;
            wptr = adv ? (wptr + 1) : wptr;
            curf = lfn;
        }
        wptr[0] = acc0;                              // curf <= 49
        wptr[1] = acc1;
    }

    __syncthreads();

    // ---- Coalesced float4 store ----
    float4* go4 = reinterpret_cast<float4*>(g_out + base_g);
    #pragma unroll 4
    for (int i = tid; i < TILE / 4; i += ROWS) go4[i] = so4[i];
}

extern "C" void kernel_launch(void* const* d_in, const int* in_sizes, int n_in,
                              void* d_out, int out_size) {
    const float* reward = (const float*)d_in[0];   // batch_reward  [B] f32
    const float* dist   = (const float*)d_in[1];   // max_next_dist [B,51] f32
    // d_in[2] = supports (linspace) — folded into the affine map, unused
    const int*   mask   = (const int*)d_in[3];     // non_final_mask[B] i32
    float* out = (float*)d_out;                    // [B,51] f32

    const int B = in_sizes[0];                     // 1048576 (divisible by 64)
    const int blocks = B / ROWS;
    c51_project_kernel<<<blocks, ROWS>>>(reward, dist, mask, out);
}

// round 4
// speedup vs baseline: 4.2945x; 1.3318x over previous
#include <cuda_runtime.h>

// C51 categorical projection, round 4.
// Single shared tile (13 KB/block instead of 26 KB) -> ~2x warps per SM.
// Each thread buffers its row into registers, the tile is then reused
// in-place as the output tile (cooperatively zeroed). Hot loop has no LDS:
// b(a) = clamp(step*a + base, 0, 50-eps), l = floor(b), u = l+1, streaming
// two-accumulator merge with fully predicated flush (l steps by 0 or 1).

static constexpr int ATOMS_C = 51;
static constexpr int ROWS    = 64;                 // rows (= threads) per block
static constexpr int TILE    = ROWS * ATOMS_C;     // 3264 floats (13056 B)

__global__ __launch_bounds__(ROWS) void c51_project_kernel(
    const float* __restrict__ g_reward,
    const float* __restrict__ g_dist,
    const int*   __restrict__ g_mask,
    float*       __restrict__ g_out)
{
    __shared__ float s_tile[TILE];

    const int tid = threadIdx.x;
    const long long base_g = (long long)blockIdx.x * TILE;

    // ---- Phase 1: coalesced float4 load of the dist tile ----
    const float4* g4 = reinterpret_cast<const float4*>(g_dist + base_g);
    float4*       s4 = reinterpret_cast<float4*>(s_tile);
    #pragma unroll
    for (int i = 0; i < TILE / 4 / ROWS; ++i)      // 12 full rounds
        s4[i * ROWS + tid] = g4[i * ROWS + tid];
    {   // remainder: TILE/4 = 816 = 12*64 + 48
        const int i = 12 * ROWS + tid;
        if (tid < 48) s4[i] = g4[i];
    }
    __syncthreads();

    // ---- Phase 2: buffer own row into registers (conflict-free stride 51) ----
    float d[ATOMS_C];
    {
        const float* __restrict__ drow = s_tile + tid * ATOMS_C;
        #pragma unroll
        for (int a = 0; a < ATOMS_C; ++a) d[a] = drow[a];
    }
    __syncthreads();

    // ---- Phase 3: cooperative zero of the tile (reused as output) ----
    const float4 z4 = make_float4(0.f, 0.f, 0.f, 0.f);
    #pragma unroll
    for (int i = 0; i < TILE / 4 / ROWS; ++i)
        s4[i * ROWS + tid] = z4;
    if (tid < 48) s4[12 * ROWS + tid] = z4;
    __syncthreads();

    // ---- Phase 4: streaming merge (no LDS in the loop) ----
    const int   r    = blockIdx.x * ROWS + tid;
    const float rw   = __ldg(g_reward + r);
    const float mk   = (float)__ldg(g_mask + r);
    const float step = 0.99f * mk;
    const float base = (rw + 10.0f) / 0.4f - 24.75f * mk;  // one div per row
    const float HI   = 49.999996f;                          // largest f32 < 50

    float* __restrict__ orow = s_tile + tid * ATOMS_C;

    float b    = fminf(fmaxf(base, 0.0f), HI);
    float curf = floorf(b);
    float* wptr = orow + (int)curf;                 // single F2I per row
    float acc1 = d[0] * (b - curf);
    float acc0 = d[0] - acc1;

    #pragma unroll
    for (int a = 1; a < ATOMS_C; ++a) {
        float bb = fmaf(step, (float)a, base);      // FFMA, imm multiplier
        bb = fminf(fmaxf(bb, 0.0f), HI);
        const float lfn = floorf(bb);               // independent per atom
        const float bm  = bb - lfn;
        const float wu  = d[a] * bm;
        const float wl  = d[a] - wu;                // d*(lf+1-b)
        const bool adv  = (lfn != curf);            // l steps by exactly 0/1
        if (adv) *wptr = acc0;                      // @P STS, converged
        const float a0 = adv ? acc1 : acc0;
        acc0 = a0 + wl;
        const float t  = acc1 + wu;
        acc1 = adv ? wu : t;
        wptr = adv ? (wptr + 1) : wptr;
        curf = lfn;
    }
    wptr[0] = acc0;                                 // curf <= 49
    wptr[1] = acc1;
    __syncthreads();

    // ---- Phase 5: coalesced float4 store ----
    float4* go4 = reinterpret_cast<float4*>(g_out + base_g);
    #pragma unroll
    for (int i = 0; i < TILE / 4 / ROWS; ++i)
        go4[i * ROWS + tid] = s4[i * ROWS + tid];
    if (tid < 48) go4[12 * ROWS + tid] = s4[12 * ROWS + tid];
}

extern "C" void kernel_launch(void* const* d_in, const int* in_sizes, int n_in,
                              void* d_out, int out_size) {
    const float* reward = (const float*)d_in[0];   // batch_reward  [B] f32
    const float* dist   = (const float*)d_in[1];   // max_next_dist [B,51] f32
    // d_in[2] = supports (linspace) — folded into the affine map, unused
    const int*   mask   = (const int*)d_in[3];     // non_final_mask[B] i32
    float* out = (float*)d_out;                    // [B,51] f32

    const int B = in_sizes[0];                     // 1048576 (divisible by 64)
    const int blocks = B / ROWS;
    c51_project_kernel<<<blocks, ROWS>>>(reward, dist, mask, out);
}

// round 5
// speedup vs baseline: 4.4398x; 1.0338x over previous
#include <cuda_runtime.h>

// C51 categorical projection, round 5.
// Each row split across 2 threads (atoms 0..25 / 26..50, the second half led
// by a zero-weight dummy atom 25 that establishes its starting bin). Halves
// the register row buffer (occupancy) and the serial merge chain (latency).
// Boundary: A defers its final two accumulators and adds them RMW after a
// sync; B's stream covers [cA, cB+1] with each bin written exactly once.

static constexpr int ATOMS_C = 51;
static constexpr int ROWS    = 64;                 // rows per block
static constexpr int THREADS = 128;                // 2 threads per row
static constexpr int TILE    = ROWS * ATOMS_C;     // 3264 floats (13056 B)
static constexpr int HALFN   = 26;                 // atoms per thread (incl. dummy)
static constexpr int V4      = TILE / 4;           // 816 float4
static constexpr int V4FULL  = (V4 / THREADS) * THREADS;   // 768
static constexpr int V4REM   = V4 - V4FULL;                // 48

__global__ __launch_bounds__(THREADS) void c51_project_kernel(
    const float* __restrict__ g_reward,
    const float* __restrict__ g_dist,
    const int*   __restrict__ g_mask,
    float*       __restrict__ g_out)
{
    __shared__ float s_tile[TILE];

    const int tid  = threadIdx.x;
    const int row  = tid & (ROWS - 1);
    const int half = tid >> 6;                     // 0: atoms 0..25, 1: 25..50
    const long long base_g = (long long)blockIdx.x * TILE;

    // ---- Phase 1: coalesced float4 load of the dist tile ----
    const float4* g4 = reinterpret_cast<const float4*>(g_dist + base_g);
    float4*       s4 = reinterpret_cast<float4*>(s_tile);
    #pragma unroll
    for (int i = 0; i < V4FULL / THREADS; ++i)
        s4[i * THREADS + tid] = g4[i * THREADS + tid];
    if (tid < V4REM) s4[V4FULL + tid] = g4[V4FULL + tid];
    __syncthreads();

    // ---- Phase 2: buffer own half-row into registers (conflict-free) ----
    float d[HALFN];
    {
        const float* __restrict__ srow = s_tile + row * ATOMS_C + half * 25;
        #pragma unroll
        for (int j = 0; j < HALFN; ++j) d[j] = srow[j];
        if (half) d[0] = 0.0f;                     // dummy atom 25: zero weight
    }
    __syncthreads();

    // ---- Phase 3: cooperative zero of the tile (reused as output) ----
    const float4 z4 = make_float4(0.f, 0.f, 0.f, 0.f);
    #pragma unroll
    for (int i = 0; i < V4FULL / THREADS; ++i)
        s4[i * THREADS + tid] = z4;
    if (tid < V4REM) s4[V4FULL + tid] = z4;
    __syncthreads();

    // ---- Phase 4a: streaming merge over this thread's 26 atoms ----
    const int   r    = blockIdx.x * ROWS + row;
    const float rw   = __ldg(g_reward + r);
    const float mk   = (float)__ldg(g_mask + r);
    const float step = 0.99f * mk;
    float base = (rw + 10.0f) / 0.4f - 24.75f * mk;      // one div per row
    base = fmaf(step, (float)(half * 25), base);          // shift to atom 25*half
    const float HI = 49.999996f;                          // largest f32 < 50

    float* __restrict__ orow = s_tile + row * ATOMS_C;

    float b    = fminf(fmaxf(base, 0.0f), HI);
    float curf = floorf(b);
    float* wptr = orow + (int)curf;                // single F2I per thread
    float acc1 = d[0] * (b - curf);                // half==1: d[0]=0 -> accs 0
    float acc0 = d[0] - acc1;

    #pragma unroll
    for (int j = 1; j < HALFN; ++j) {
        float bb = fmaf(step, (float)j, base);     // FFMA, imm multiplier
        bb = fminf(fmaxf(bb, 0.0f), HI);
        const float lfn = floorf(bb);              // independent per atom
        const float bm  = bb - lfn;
        const float wu  = d[j] * bm;
        const float wl  = d[j] - wu;               // d*(lf+1-b)
        const bool adv  = (lfn != curf);           // l steps by exactly 0/1
        if (adv) *wptr = acc0;                     // @P STS, converged
        const float a0 = adv ? acc1 : acc0;
        acc0 = a0 + wl;
        const float t  = acc1 + wu;
        acc1 = adv ? wu : t;
        wptr = adv ? (wptr + 1) : wptr;
        curf = lfn;
    }
    if (half) {                                    // B: plain final flush
        wptr[0] = acc0;                            // covers [cA, cB+1] exactly once
        wptr[1] = acc1;
    }
    __syncthreads();
    if (!half) {                                   // A: deferred carry, RMW add
        wptr[0] += acc0;                           // bins [cA, cA+1] in B's region
        wptr[1] += acc1;
    }
    __syncthreads();

    // ---- Phase 5: coalesced float4 store ----
    float4* go4 = reinterpret_cast<float4*>(g_out + base_g);
    #pragma unroll
    for (int i = 0; i < V4FULL / THREADS; ++i)
        go4[i * THREADS + tid] = s4[i * THREADS + tid];
    if (tid < V4REM) go4[V4FULL + tid] = s4[V4FULL + tid];
}

extern "C" void kernel_launch(void* const* d_in, const int* in_sizes, int n_in,
                              void* d_out, int out_size) {
    const float* reward = (const float*)d_in[0];   // batch_reward  [B] f32
    const float* dist   = (const float*)d_in[1];   // max_next_dist [B,51] f32
    // d_in[2] = supports (linspace) — folded into the affine map, unused
    const int*   mask   = (const int*)d_in[3];     // non_final_mask[B] i32
    float* out = (float*)d_out;                    // [B,51] f32

    const int B = in_sizes[0];                     // 1048576 (divisible by 64)
    const int blocks = B / ROWS;
    c51_project_kernel<<<blocks, THREADS>>>(reward, dist, mask, out);
}